// round 16
// baseline (speedup 1.0000x reference)
#include <cuda_runtime.h>

#define Nn      1000
#define INF_    32
#define Hh      128
#define Mm      128
#define DEGc    16
#define Pp      2
#define OUTn    10
#define NSTART  64
#define MAXM    10000
#define MSGCAP  640
#define Bw      16
#define P2B     148
#define THRv    (1.0f - 1e-7f)

typedef unsigned long long ull;
typedef unsigned short u16;
typedef unsigned char u8;

__device__ float g_feats[Nn*Hh];
__device__ float g_msgs[MSGCAP*Mm];
__device__ float g_xsave[MSGCAP*256];
__device__ u8    g_mats[MSGCAP];
__device__ u16   g_qn2[MAXM];
__device__ float g_tact2[Nn];
__device__ int   g_hh[4];
__device__ float g_part[(Nn+1)*128];

__device__ __forceinline__ ull pack2(float a, float b){
    ull r; asm("mov.b64 %0, {%1,%2};" : "=l"(r) : "f"(a), "f"(b)); return r;
}
__device__ __forceinline__ ull fma2(ull a, ull b, ull c){
    ull d; asm("fma.rn.f32x2 %0, %1, %2, %3;" : "=l"(d) : "l"(a), "l"(b), "l"(c)); return d;
}
__device__ __forceinline__ ull add2(ull a, ull b){
    ull d; asm("add.rn.f32x2 %0, %1, %2;" : "=l"(d) : "l"(a), "l"(b)); return d;
}
__device__ __forceinline__ float2 unp(ull a){
    float2 f; asm("mov.b64 {%0,%1}, %2;" : "=f"(f.x), "=f"(f.y) : "l"(a)); return f;
}
#define TREE(ap) { ap += __shfl_xor_sync(~0u, ap, 16); ap += __shfl_xor_sync(~0u, ap, 8); \
                   ap += __shfl_xor_sync(~0u, ap, 4);  ap += __shfl_xor_sync(~0u, ap, 2); \
                   ap += __shfl_xor_sync(~0u, ap, 1); }

__global__ void enc_kernel(const float* __restrict__ xa,
                           const float* __restrict__ ew,
                           const float* __restrict__ eb)
{
    __shared__ float sx[INF_];
    int nrow = blockIdx.x;
    if (threadIdx.x < INF_) sx[threadIdx.x] = xa[nrow*INF_ + threadIdx.x];
    __syncthreads();
    int h = threadIdx.x;
    float a = eb[h];
    #pragma unroll
    for (int i = 0; i < INF_; i++) a = fmaf(sx[i], ew[i*Hh + h], a);
    g_feats[nrow*Hh + h] = a;
}

// ---- phase-1 shared layout (float units) ----
#define OFF_NSW  0
#define OFF_PART 32768
#define OFF_XF   40960
#define OFF_XM   43008
#define OFF_QN   45056
#define OFF_TACT 50064
#define OFF_AW   51064
#define OFF_NSB  51320
#define OFF_NMB  51448
#define OFF_G    51576
#define OFF_NBR  51704
#define OFF_LN   51960
#define OFF_LI   51992
#define OFF_SLOT 52024
#define OFF_MIDX 52056
#define OFF_NA   52088
#define OFF_ACTP 52104
#define OFF_ACTM 52168
#define OFF_CTL  52232
#define OFF_AB   52240
#define OFF_MATS 52244
#define OFF_NEWL 52404
#define SMEM_FLOATS 52436
#define SMEM_BYTES  (SMEM_FLOATS*4)

__device__ __forceinline__ void scan_window(float* sm, int lane, int mprev, int bufn)
{
    int* ctl = (int*)(sm + OFF_CTL);
    u16* qn  = (u16*)(sm + OFF_QN);
    float* tact = sm + OFF_TACT;
    int* ln = (int*)(sm + OFF_LN) + bufn*Bw;
    int* li = (int*)(sm + OFF_LI) + bufn*Bw;
    int* sl = (int*)(sm + OFF_SLOT) + bufn*Bw;
    int* mi = (int*)(sm + OFF_MIDX) + bufn*Bw;
    int* nw = (int*)(sm + OFF_NEWL) + bufn*Bw;
    u8*  mats = (u8*)(sm + OFF_MATS);
    if (lane == 0) { ctl[2] += mprev; ctl[1] += DEGc*mprev; }
    __syncwarp();
    int pos = ctl[0], tail = ctl[1];
    if (tail >= MAXM) { if (lane == 0) ctl[3] = 2; return; }
    int lim = tail;
    int mq = 0, rewind = -1;
    while (pos < lim && mq < Bw) {
        int bl = lim - pos; if (bl > 32) bl = 32;
        int idx = pos + lane;
        bool valid = lane < bl;
        int raw = valid ? (int)qn[idx] : 0x8000;
        int nodel = raw & 0x7FFF;
        bool cons = (raw & 0x8000) != 0;
        float ta = (valid && !cons) ? tact[nodel] : 2.0f;
        unsigned prod = __ballot_sync(~0u, valid && !cons && ta <= THRv);
        unsigned peers = __match_any_sync(~0u, nodel);
        bool dup = false;
        if ((prod >> lane) & 1) {
            dup = (peers & prod & ((1u << lane) - 1u)) != 0;
            for (int i = 0; i < mq; i++) dup |= (nodel == ln[i]);
        }
        unsigned dupm = __ballot_sync(~0u, dup);
        unsigned keep = prod & ~dupm;
        int room = Bw - mq, cnt = __popc(keep);
        int clip = 33;
        if (cnt > room) {
            unsigned k2 = keep;
            for (int z = 0; z < room; z++) k2 &= k2 - 1u;
            clip = __ffs(k2) - 1;
            keep &= (1u << clip) - 1u;
            cnt = room;
        }
        unsigned defer = dupm & ((clip < 33) ? ((1u << clip) - 1u) : ~0u);
        int firstdef = defer ? (pos + __ffs(defer) - 1)
                             : (clip < 33 ? pos + clip : -1);
        if ((keep >> lane) & 1) {
            int rk = __popc(keep & ((1u << lane) - 1u));
            ln[mq + rk] = nodel; li[mq + rk] = idx;
            qn[idx] = (u16)(raw | 0x8000);
        }
        __syncwarp();
        mq += cnt;
        if (firstdef >= 0 && rewind < 0) rewind = firstdef;
        pos += bl;
        if (clip < 33) break;
    }
    __syncwarp();
    int key = -(lane + 1), idxe = 0;
    if (lane < mq) {
        idxe = li[lane];
        key = (idxe < NSTART) ? idxe : NSTART + ((idxe - NSTART) >> 4);
    }
    unsigned pk = __match_any_sync(~0u, key);
    int leader = __ffs(pk) - 1;
    unsigned lm = __ballot_sync(~0u, (leader == lane) && (lane < mq));
    int nsl = __popc(lm);
    if (lane < mq) {
        int slot = __popc(lm & ((1u << leader) - 1u));
        sl[lane] = slot;
        if (leader == lane) mi[slot] = idxe;
    }
    __syncwarp();
    bool isnew = false;
    if (lane < nsl) {
        int mx = mi[lane];
        isnew = (mx >= NSTART) && !mats[(mx - NSTART) >> 4];
    }
    unsigned nb = __ballot_sync(~0u, isnew);
    if (isnew) nw[__popc(nb & ((1u << lane) - 1u))] = lane;
    if (lane == 0) {
        ctl[0] = (rewind >= 0) ? rewind : pos;
        ctl[4] = mq; ctl[5] = nsl; ctl[6] = __popc(nb);
        if (mq == 0) ctl[3] = 1;
    }
}

__global__ void __launch_bounds__(1024, 1) serial_kernel(
    const float* __restrict__ fm,  const int*   __restrict__ nbr,
    const float* __restrict__ nsw, const float* __restrict__ nsb,
    const float* __restrict__ nmw, const float* __restrict__ nmb,
    const float* __restrict__ aw,  const float* __restrict__ ab)
{
    extern __shared__ float sm[];
    ull*   s_nsw2 = (ull*)(sm + OFF_NSW);
    ull*   s_part2= (ull*)(sm + OFF_PART);
    float* s_xf   = sm + OFF_XF;
    float* s_xm   = sm + OFF_XM;
    u16*   s_qn16 = (u16*)(sm + OFF_QN);
    float* s_tact = sm + OFF_TACT;
    float* s_aw   = sm + OFF_AW;
    float* s_nsb  = sm + OFF_NSB;
    float* s_nmb  = sm + OFF_NMB;
    float* s_g    = sm + OFF_G;
    int*   s_nbr  = (int*)(sm + OFF_NBR);
    float* s_na   = sm + OFF_NA;
    float* s_actp = sm + OFF_ACTP;
    float* s_actm = sm + OFF_ACTM;
    u8*    s_mats = (u8*)(sm + OFF_MATS);
    int*   ctl    = (int*)(sm + OFF_CTL);

    const int t = threadIdx.x;
    const int w = t >> 5, l = t & 31;

    for (int i = t; i < (256*Hh)/4; i += 1024)
        ((float4*)(sm + OFF_NSW))[i] = ((const float4*)nsw)[i];
    if (t < 256) s_aw[t] = aw[t];
    if (t < 128) { s_nsb[t] = nsb[t]; s_nmb[t] = nmb[t]; s_g[t] = 0.f; }
    if (t < Nn)  s_tact[t] = 0.f;
    if (t < NSTART) s_qn16[t] = (u16)t;
    if (t < MSGCAP) s_mats[t] = 0;
    if (t == 0) {
        ctl[0] = 0; ctl[1] = NSTART; ctl[2] = 0; ctl[3] = 0; ctl[6] = 0;
        sm[OFF_AB] = ab[0];
    }
    ull wnm[16];
    {
        int kc = w >> 1, j2 = ((w & 1) << 5) | l;
        #pragma unroll
        for (int i = 0; i < 16; i++) {
            float2 v = *(const float2*)(nmw + (16*kc + i)*Hh + 2*j2);
            wnm[i] = pack2(v.x, v.y);
        }
    }
    __syncthreads();
    if (w == 0) scan_window(sm, l, 0, 0);
    __syncthreads();

    int buf = 0;
    for (;;) {
        if (ctl[3]) break;
        const int m = ctl[4], nsl = ctl[5], nnew = ctl[6];
        const int tail = ctl[1], pcb = ctl[2];
        const int* s_ln    = (const int*)(sm + OFF_LN)   + buf*Bw;
        const int* s_slotb = (const int*)(sm + OFF_SLOT) + buf*Bw;
        const int* s_midxb = (const int*)(sm + OFF_MIDX) + buf*Bw;
        const int* s_newl  = (const int*)(sm + OFF_NEWL) + buf*Bw;

        // ---- G0 ----
        {
            int k = t & 127, wig = (t >> 5) & 3;
            #pragma unroll
            for (int h2 = 0; h2 < 2; h2++) {
                int e = (t >> 7) + h2*8;
                if (e < m) {
                    int node = s_ln[e];
                    float f1 = g_feats[node*Hh + k];
                    s_xf[e*128 + k] = f1;
                    float ap = f1 * s_aw[k];
                    TREE(ap);
                    if (l == 0) s_actp[e*4 + wig] = ap;
                    if (k < DEGc) s_nbr[e*DEGc + k] = nbr[node*DEGc + k];
                }
                if (e < nsl) {
                    int midx = s_midxb[e];
                    bool oldok = (midx < NSTART) || s_mats[(midx - NSTART) >> 4];
                    if (oldok) {
                        const float* mp = (midx < NSTART) ? (fm + midx*Mm)
                                         : (g_msgs + ((midx - NSTART) >> 4)*Mm);
                        float f2 = mp[k];
                        s_xm[e*128 + k] = f2;
                        float am = f2 * s_aw[128 + k];
                        TREE(am);
                        if (l == 0) s_actm[e*4 + wig] = am;
                    }
                }
            }
        }
        __syncthreads();

        // ---- on-demand message materialization ----
        for (int c = 0; c*4 < nnew; c++) {
            {
                int kc = w >> 1, j2 = ((w & 1) << 5) | l;
                const float4* xp[4];
                #pragma unroll
                for (int el = 0; el < 4; el++) {
                    int sp = c*4 + el;
                    int p = 0;
                    if (sp < nnew) p = (s_midxb[s_newl[sp]] - NSTART) >> 4;
                    xp[el] = (const float4*)(g_xsave + p*256 + kc*16);
                }
                ull a0=0, a1=0, a2=0, a3=0;
                #pragma unroll
                for (int q = 0; q < 4; q++) {
                    ull w0 = wnm[4*q], w1 = wnm[4*q+1], w2 = wnm[4*q+2], w3 = wnm[4*q+3];
                    float4 x0 = xp[0][q], x1 = xp[1][q], x2 = xp[2][q], x3 = xp[3][q];
                    a0 = fma2(pack2(x0.x,x0.x), w0, a0);
                    a0 = fma2(pack2(x0.y,x0.y), w1, a0);
                    a0 = fma2(pack2(x0.z,x0.z), w2, a0);
                    a0 = fma2(pack2(x0.w,x0.w), w3, a0);
                    a1 = fma2(pack2(x1.x,x1.x), w0, a1);
                    a1 = fma2(pack2(x1.y,x1.y), w1, a1);
                    a1 = fma2(pack2(x1.z,x1.z), w2, a1);
                    a1 = fma2(pack2(x1.w,x1.w), w3, a1);
                    a2 = fma2(pack2(x2.x,x2.x), w0, a2);
                    a2 = fma2(pack2(x2.y,x2.y), w1, a2);
                    a2 = fma2(pack2(x2.z,x2.z), w2, a2);
                    a2 = fma2(pack2(x2.w,x2.w), w3, a2);
                    a3 = fma2(pack2(x3.x,x3.x), w0, a3);
                    a3 = fma2(pack2(x3.y,x3.y), w1, a3);
                    a3 = fma2(pack2(x3.z,x3.z), w2, a3);
                    a3 = fma2(pack2(x3.w,x3.w), w3, a3);
                }
                ull* pp = s_part2 + kc*64 + j2;
                pp[0] = a0; pp[1024] = a1; pp[2048] = a2; pp[3072] = a3;
            }
            __syncthreads();
            if (t < 256) {
                int el = t >> 6, j2 = t & 63, sp = c*4 + el;
                if (sp < nnew) {
                    int slot = s_newl[sp];
                    int p = (s_midxb[slot] - NSTART) >> 4;
                    ull s = s_part2[el*1024 + j2];
                    #pragma unroll
                    for (int kc = 1; kc < 16; kc++)
                        s = add2(s, s_part2[el*1024 + kc*64 + j2]);
                    float2 v = unp(s);
                    float2 o; o.x = v.x + s_nmb[2*j2]; o.y = v.y + s_nmb[2*j2+1];
                    *(float2*)(g_msgs + p*Mm + 2*j2) = o;
                    *(float2*)(s_xm + slot*128 + 2*j2) = o;
                    if (j2 == 0) s_mats[p] = 1;
                }
            }
            __syncthreads();
            if (w < 16) {
                int sp = c*4 + (w >> 2);
                if (sp < nnew) {
                    int slot = s_newl[sp], wig = w & 3;
                    float am = s_xm[slot*128 + wig*32 + l] * s_aw[128 + wig*32 + l];
                    TREE(am);
                    if (l == 0) s_actm[slot*4 + wig] = am;
                }
            }
            __syncthreads();
        }

        // ---- NS: 16 warps x 8 entries (weights read once per 8 entries) ----
        if (w < 16) {
            int half = w >> 3, w7 = w & 7;
            int grp8 = w7 >> 2, kc = (w7 >> 1) & 1, j2 = ((w7 & 1) << 5) | l;
            const ull* wb; const float4* xb; ull* pb; bool act;
            if (half == 0) {
                wb = s_nsw2 + (size_t)(kc*64)*64 + j2;
                xb = (const float4*)(s_xf + grp8*1024 + kc*64);
                pb = s_part2 + (size_t)(grp8*8)*128 + kc*64 + j2;
                act = (grp8*8 < m);
            } else {
                wb = s_nsw2 + (size_t)(128 + kc*64)*64 + j2;
                xb = (const float4*)(s_xm + grp8*1024 + kc*64);
                pb = s_part2 + 2048 + (size_t)(grp8*8)*128 + kc*64 + j2;
                act = (grp8*8 < nsl);
            }
            if (act) {
                ull acc[8] = {0,0,0,0,0,0,0,0};
                #pragma unroll
                for (int q = 0; q < 16; q++) {
                    ull w0 = wb[(4*q  )*64], w1 = wb[(4*q+1)*64];
                    ull w2 = wb[(4*q+2)*64], w3 = wb[(4*q+3)*64];
                    #pragma unroll
                    for (int el = 0; el < 8; el++) {
                        float4 x = xb[el*32 + q];
                        acc[el] = fma2(pack2(x.x,x.x), w0, acc[el]);
                        acc[el] = fma2(pack2(x.y,x.y), w1, acc[el]);
                        acc[el] = fma2(pack2(x.z,x.z), w2, acc[el]);
                        acc[el] = fma2(pack2(x.w,x.w), w3, acc[el]);
                    }
                }
                #pragma unroll
                for (int el = 0; el < 8; el++) pb[el*128] = acc[el];
            }
        }
        __syncthreads();

        // ---- R ----
        if (t < 512) {
            int j2 = t & 63;
            #pragma unroll
            for (int h2 = 0; h2 < 2; h2++) {
                int e = (t >> 6) + h2*8;
                if (e < m) {
                    int sle = s_slotb[e];
                    ull s = s_part2[e*128 + j2];
                    s = add2(s, s_part2[e*128 + 64 + j2]);
                    s = add2(s, s_part2[2048 + sle*128 + j2]);
                    s = add2(s, s_part2[2048 + sle*128 + 64 + j2]);
                    float2 v = unp(s);
                    float2 o;
                    o.x = fmaxf(v.x + s_nsb[2*j2],     0.f);
                    o.y = fmaxf(v.y + s_nsb[2*j2 + 1], 0.f);
                    *(float2*)(s_xf + e*128 + 2*j2) = o;
                }
            }
        } else if (t < 528) {
            int e = t - 512;
            if (e < m) {
                int sle = s_slotb[e];
                float z = sm[OFF_AB]
                        + s_actp[e*4] + s_actp[e*4+1] + s_actp[e*4+2] + s_actp[e*4+3]
                        + s_actm[sle*4] + s_actm[sle*4+1] + s_actm[sle*4+2] + s_actm[sle*4+3];
                float cand = 1.f / (1.f + expf(-z));
                int node = s_ln[e];
                float ta = s_tact[node];
                float na = (ta + cand > 1.0f) ? (1.0f - ta) : cand;
                s_na[e] = na;
                s_tact[node] = ta + na;
            }
        } else if (t >= 640 && t < 896) {
            int rel = t - 640, e = rel >> 4, d = rel & 15;
            if (e < m) {
                int qp = tail + e*DEGc + d;
                if (qp < MAXM) s_qn16[qp] = (u16)s_nbr[e*DEGc + d];
            }
        }
        __syncthreads();

        // ---- C ----
        if (t < 512) {
            int j2 = t & 63;
            #pragma unroll
            for (int h2 = 0; h2 < 2; h2++) {
                int e = (t >> 6) + h2*8;
                if (e < m) {
                    float2 o = *(const float2*)(s_xf + e*128 + 2*j2);
                    *(float2*)(g_feats + s_ln[e]*Hh + 2*j2) = o;
                    *(float2*)(g_xsave + (pcb + e)*256 + 2*j2) = o;
                }
            }
        } else if (t < 640) {
            int k = t - 512;
            float acc = s_g[k];
            #pragma unroll
            for (int e = 0; e < Bw; e++)
                if (e < m) acc = fmaf(s_xf[e*128 + k], s_na[e], acc);
            s_g[k] = acc;
        } else if (t < 960) {
            for (int j = t - 640; j < 2048; j += 320) {
                int e = j >> 7, k = j & 127;
                if (e < m)
                    g_xsave[(pcb + e)*256 + 128 + k] = s_xm[s_slotb[e]*128 + k];
            }
        } else if (w == 31) {
            scan_window(sm, l, m, buf ^ 1);
        }
        __syncthreads();
        buf ^= 1;
    }

    // ---- handoff dump ----
    for (int i = t; i < Nn; i += 1024) g_tact2[i] = s_tact[i];
    for (int i = t; i < MAXM/2; i += 1024)
        ((unsigned*)g_qn2)[i] = ((const unsigned*)s_qn16)[i];
    for (int i = t; i < MSGCAP/4; i += 1024)
        ((unsigned*)g_mats)[i] = ((const unsigned*)s_mats)[i];
    if (t < 128) g_part[Nn*128 + t] = s_g[t];
    if (t == 0) { g_hh[0] = ctl[0]; g_hh[1] = ctl[1]; g_hh[2] = ctl[2]; }
}

// ---- deferred message kernel ----
__global__ void __launch_bounds__(64, 1) msg_kernel(
    const float* __restrict__ nmw, const float* __restrict__ nmb)
{
    int t = threadIdx.x;
    int pcn = g_hh[2];
    for (int pc = blockIdx.x; pc < pcn; pc += P2B) {
        if (g_mats[pc]) continue;
        int j2 = t;
        ull acc[16];
        #pragma unroll
        for (int kc = 0; kc < 16; kc++) {
            ull a = 0ull;
            #pragma unroll
            for (int q = 0; q < 4; q++) {
                float4 x = *(const float4*)(g_xsave + pc*256 + kc*16 + 4*q);
                const ull* wr = (const ull*)(nmw + (kc*16 + 4*q)*Hh + 2*j2);
                a = fma2(pack2(x.x, x.x), wr[0],   a);
                a = fma2(pack2(x.y, x.y), wr[64],  a);
                a = fma2(pack2(x.z, x.z), wr[128], a);
                a = fma2(pack2(x.w, x.w), wr[192], a);
            }
            acc[kc] = a;
        }
        ull s = acc[0];
        #pragma unroll
        for (int kc = 1; kc < 16; kc++) s = add2(s, acc[kc]);
        float2 v = unp(s);
        float2 o; o.x = v.x + nmb[2*j2]; o.y = v.y + nmb[2*j2+1];
        *(float2*)(g_msgs + pc*Mm + 2*j2) = o;
    }
}

// ---- phase 2: one block per node; weights via L1 (no smem cache) ----
__global__ void __launch_bounds__(128, 8) tail_kernel(
    const float* __restrict__ fm,
    const float* __restrict__ nsw, const float* __restrict__ nsb,
    const float* __restrict__ aw,  const float* __restrict__ ab)
{
    __shared__ float s_xf[128], s_xm[128], s_aw2[256], s_nsb2[128], s_gl[128];
    __shared__ u16 s_li[512];
    __shared__ int s_c[1], s_wc[4];
    __shared__ float s_f[2];

    const int node = blockIdx.x;
    const int t = threadIdx.x, w = t >> 5, l = t & 31;

    if (t < 128) g_part[node*128 + t] = 0.f;       // default (may overwrite)
    if (g_tact2[node] > THRv) return;              // halted at handoff: no work

    if (t < 128) { s_aw2[t] = aw[t]; s_aw2[128+t] = aw[128+t];
                   s_nsb2[t] = nsb[t]; s_gl[t] = 0.f; }
    if (t == 0) { s_c[0] = 0; s_f[1] = ab[0]; }
    __syncthreads();

    const int head0 = g_hh[0];
    const int lim2  = g_hh[1] < MAXM ? g_hh[1] : MAXM;

    // harvest this node's unconsumed entries in idx order
    for (int base = head0; base < lim2; base += 128) {
        int idx = base + t;
        bool vv = idx < lim2;
        int raw = vv ? (int)g_qn2[idx] : 0x8000;
        bool cand = vv && (raw == node);           // bit15 clear + node match
        unsigned bal = __ballot_sync(~0u, cand);
        if (l == 0) s_wc[w] = __popc(bal);
        __syncthreads();
        int cbase = s_c[0];
        #pragma unroll
        for (int q = 0; q < 4; q++) if (q < w) cbase += s_wc[q];
        if (cand) {
            int p = cbase + __popc(bal & ((1u << l) - 1u));
            if (p < 512) s_li[p] = (u16)idx;
        }
        __syncthreads();
        if (t == 0) {
            int nc = s_c[0] + s_wc[0] + s_wc[1] + s_wc[2] + s_wc[3];
            s_c[0] = nc < 512 ? nc : 512;
        }
        __syncthreads();
    }
    const int cnt = s_c[0];

    float tav = g_tact2[node];
    for (int i = 0; i < cnt; i++) {
        if (tav > THRv) break;                     // chain halted
        const int idx = (int)s_li[i];
        if (t < 128) {
            s_xf[t] = g_feats[node*Hh + t];
            const float* mp = (idx < NSTART) ? (fm + idx*Mm)
                             : (g_msgs + ((idx - NSTART) >> 4)*Mm);
            s_xm[t] = mp[t];
        }
        __syncthreads();

        float2 o = make_float2(0.f, 0.f);
        if (w < 2) {
            const int j2 = w*32 + l;
            const ull* wb = (const ull*)nsw + j2;
            ull acc[4] = {0ull, 0ull, 0ull, 0ull};
            #pragma unroll
            for (int h = 0; h < 4; h++) {
                const float4* xv = (h < 2) ? ((const float4*)s_xf + (h & 1)*16)
                                           : ((const float4*)s_xm + (h & 1)*16);
                const ull* wh = wb + (size_t)(h*64)*64;
                #pragma unroll
                for (int q = 0; q < 16; q++) {
                    float4 x = xv[q];
                    acc[h] = fma2(pack2(x.x, x.x), wh[(4*q  )*64], acc[h]);
                    acc[h] = fma2(pack2(x.y, x.y), wh[(4*q+1)*64], acc[h]);
                    acc[h] = fma2(pack2(x.z, x.z), wh[(4*q+2)*64], acc[h]);
                    acc[h] = fma2(pack2(x.w, x.w), wh[(4*q+3)*64], acc[h]);
                }
            }
            ull s = add2(add2(add2(acc[0], acc[1]), acc[2]), acc[3]);
            float2 v = unp(s);
            o.x = fmaxf(v.x + s_nsb2[2*j2],     0.f);
            o.y = fmaxf(v.y + s_nsb2[2*j2 + 1], 0.f);
        } else if (w == 2) {
            float pf[4], pm[4];
            #pragma unroll
            for (int g = 0; g < 4; g++) {
                float ap = s_xf[g*32 + l] * s_aw2[g*32 + l];
                TREE(ap); pf[g] = ap;
            }
            #pragma unroll
            for (int g = 0; g < 4; g++) {
                float am = s_xm[g*32 + l] * s_aw2[128 + g*32 + l];
                TREE(am); pm[g] = am;
            }
            if (l == 0) {
                float z = s_f[1] + pf[0] + pf[1] + pf[2] + pf[3]
                                 + pm[0] + pm[1] + pm[2] + pm[3];
                float cd = 1.f / (1.f + expf(-z));
                float na = (tav + cd > 1.0f) ? (1.0f - tav) : cd;
                s_f[0] = na;
            }
        }
        __syncthreads();

        if (w < 2) {
            const int j2 = w*32 + l;
            float na = s_f[0];
            *(float2*)(g_feats + node*Hh + 2*j2) = o;
            s_gl[2*j2]     += o.x * na;
            s_gl[2*j2 + 1] += o.y * na;
        }
        tav += s_f[0];
        __syncthreads();
    }

    if (t == 0) g_tact2[node] = tav;
    if (t < 128) g_part[node*128 + t] = s_gl[t];
}

__global__ void __launch_bounds__(1024, 1) decode_kernel(
    const float* __restrict__ dw, const float* __restrict__ db,
    float* __restrict__ out)
{
    __shared__ float sp2[8*128];
    __shared__ float sg[128];
    __shared__ float sc[32];
    int t = threadIdx.x;
    {
        int col = t & 127, seg = t >> 7;
        float a = 0.f;
        for (int b = seg; b <= Nn; b += 8) a += g_part[b*128 + col];
        sp2[seg*128 + col] = a;
    }
    __syncthreads();
    if (t < 128) {
        float a = sp2[t];
        #pragma unroll
        for (int s = 1; s < 8; s++) a += sp2[s*128 + t];
        sg[t] = a;
    }
    __syncthreads();
    if (t < Pp*OUTn) {
        int p = t / OUTn, o = t % OUTn;
        float z = db[p*OUTn + o];
        #pragma unroll 8
        for (int h = 0; h < Hh; h++) z = fmaf(sg[h], dw[(p*Hh + h)*OUTn + o], z);
        sc[t] = z;
    }
    __syncthreads();
    if (t < Pp) {
        float mx = -1e30f;
        for (int o = 0; o < OUTn; o++) mx = fmaxf(mx, sc[t*OUTn + o]);
        float se = 0.f;
        for (int o = 0; o < OUTn; o++) se += expf(sc[t*OUTn + o] - mx);
        float ls = logf(se);
        for (int o = 0; o < OUTn; o++) out[t*OUTn + o] = sc[t*OUTn + o] - mx - ls;
    }
}

extern "C" void kernel_launch(void* const* d_in, const int* in_sizes, int n_in,
                              void* d_out, int out_size)
{
    const float* xa  = (const float*)d_in[0];
    const float* fm  = (const float*)d_in[1];
    const int*   nbv = (const int*)  d_in[2];
    const float* ew  = (const float*)d_in[4];
    const float* eb  = (const float*)d_in[5];
    const float* nsw = (const float*)d_in[6];
    const float* nsb = (const float*)d_in[7];
    const float* nmw = (const float*)d_in[8];
    const float* nmb = (const float*)d_in[9];
    const float* aw  = (const float*)d_in[10];
    const float* ab  = (const float*)d_in[11];
    const float* dw  = (const float*)d_in[12];
    const float* db  = (const float*)d_in[13];
    float* out = (float*)d_out;

    cudaFuncSetAttribute(serial_kernel,
                         cudaFuncAttributeMaxDynamicSharedMemorySize, SMEM_BYTES);

    enc_kernel<<<Nn, Hh>>>(xa, ew, eb);
    serial_kernel<<<1, 1024, SMEM_BYTES>>>(fm, nbv, nsw, nsb, nmw, nmb, aw, ab);
    msg_kernel<<<P2B, 64>>>(nmw, nmb);
    tail_kernel<<<Nn, 128>>>(fm, nsw, nsb, aw, ab);
    decode_kernel<<<1, 1024>>>(dw, db, out);
}

// round 17
// speedup vs baseline: 1.1655x; 1.1655x over previous
#include <cuda_runtime.h>

#define Nn      1000
#define INF_    32
#define Hh      128
#define Mm      128
#define DEGc    16
#define Pp      2
#define OUTn    10
#define NSTART  64
#define MAXM    10000
#define MSGCAP  640
#define Bw      16
#define P2B     148
#define THRv    (1.0f - 1e-7f)

typedef unsigned long long ull;
typedef unsigned short u16;
typedef unsigned char u8;

__device__ float g_feats[Nn*Hh];
__device__ float g_msgs[MSGCAP*Mm];
__device__ float g_xsave[MSGCAP*256];
__device__ u8    g_mats[MSGCAP];
__device__ u16   g_qn2[MAXM];
__device__ float g_tact2[Nn];
__device__ int   g_hh[4];
__device__ float g_part[(Nn+1)*128];

__device__ __forceinline__ ull pack2(float a, float b){
    ull r; asm("mov.b64 %0, {%1,%2};" : "=l"(r) : "f"(a), "f"(b)); return r;
}
__device__ __forceinline__ ull fma2(ull a, ull b, ull c){
    ull d; asm("fma.rn.f32x2 %0, %1, %2, %3;" : "=l"(d) : "l"(a), "l"(b), "l"(c)); return d;
}
__device__ __forceinline__ ull add2(ull a, ull b){
    ull d; asm("add.rn.f32x2 %0, %1, %2;" : "=l"(d) : "l"(a), "l"(b)); return d;
}
__device__ __forceinline__ float2 unp(ull a){
    float2 f; asm("mov.b64 {%0,%1}, %2;" : "=f"(f.x), "=f"(f.y) : "l"(a)); return f;
}
#define TREE(ap) { ap += __shfl_xor_sync(~0u, ap, 16); ap += __shfl_xor_sync(~0u, ap, 8); \
                   ap += __shfl_xor_sync(~0u, ap, 4);  ap += __shfl_xor_sync(~0u, ap, 2); \
                   ap += __shfl_xor_sync(~0u, ap, 1); }

__global__ void enc_kernel(const float* __restrict__ xa,
                           const float* __restrict__ ew,
                           const float* __restrict__ eb)
{
    __shared__ float sx[INF_];
    int nrow = blockIdx.x;
    if (threadIdx.x < INF_) sx[threadIdx.x] = xa[nrow*INF_ + threadIdx.x];
    __syncthreads();
    int h = threadIdx.x;
    float a = eb[h];
    #pragma unroll
    for (int i = 0; i < INF_; i++) a = fmaf(sx[i], ew[i*Hh + h], a);
    g_feats[nrow*Hh + h] = a;
}

// ---- phase-1 shared layout (float units) ----
#define OFF_NSW  0
#define OFF_PART 32768
#define OFF_XF   40960
#define OFF_XM   43008
#define OFF_QN   45056
#define OFF_TACT 50064
#define OFF_AW   51064
#define OFF_NSB  51320
#define OFF_NMB  51448
#define OFF_G    51576
#define OFF_NBR  51704
#define OFF_LN   51960
#define OFF_LI   51992
#define OFF_SLOT 52024
#define OFF_MIDX 52056
#define OFF_NA   52088
#define OFF_ACTP 52104
#define OFF_ACTM 52168
#define OFF_CTL  52232
#define OFF_AB   52240
#define OFF_MATS 52244
#define OFF_NEWL 52404
#define SMEM_FLOATS 52436
#define SMEM_BYTES  (SMEM_FLOATS*4)

__device__ __forceinline__ void scan_window(float* sm, int lane, int mprev, int bufn)
{
    int* ctl = (int*)(sm + OFF_CTL);
    u16* qn  = (u16*)(sm + OFF_QN);
    float* tact = sm + OFF_TACT;
    int* ln = (int*)(sm + OFF_LN) + bufn*Bw;
    int* li = (int*)(sm + OFF_LI) + bufn*Bw;
    int* sl = (int*)(sm + OFF_SLOT) + bufn*Bw;
    int* mi = (int*)(sm + OFF_MIDX) + bufn*Bw;
    int* nw = (int*)(sm + OFF_NEWL) + bufn*Bw;
    u8*  mats = (u8*)(sm + OFF_MATS);
    if (lane == 0) { ctl[2] += mprev; ctl[1] += DEGc*mprev; }
    __syncwarp();
    int pos = ctl[0], tail = ctl[1];
    if (tail >= MAXM) { if (lane == 0) ctl[3] = 2; return; }
    int lim = tail;
    int mq = 0, rewind = -1;
    while (pos < lim && mq < Bw) {
        int bl = lim - pos; if (bl > 32) bl = 32;
        int idx = pos + lane;
        bool valid = lane < bl;
        int raw = valid ? (int)qn[idx] : 0x8000;
        int nodel = raw & 0x7FFF;
        bool cons = (raw & 0x8000) != 0;
        float ta = (valid && !cons) ? tact[nodel] : 2.0f;
        unsigned prod = __ballot_sync(~0u, valid && !cons && ta <= THRv);
        unsigned peers = __match_any_sync(~0u, nodel);
        bool dup = false;
        if ((prod >> lane) & 1) {
            dup = (peers & prod & ((1u << lane) - 1u)) != 0;
            for (int i = 0; i < mq; i++) dup |= (nodel == ln[i]);
        }
        unsigned dupm = __ballot_sync(~0u, dup);
        unsigned keep = prod & ~dupm;
        int room = Bw - mq, cnt = __popc(keep);
        int clip = 33;
        if (cnt > room) {
            unsigned k2 = keep;
            for (int z = 0; z < room; z++) k2 &= k2 - 1u;
            clip = __ffs(k2) - 1;
            keep &= (1u << clip) - 1u;
            cnt = room;
        }
        unsigned defer = dupm & ((clip < 33) ? ((1u << clip) - 1u) : ~0u);
        int firstdef = defer ? (pos + __ffs(defer) - 1)
                             : (clip < 33 ? pos + clip : -1);
        if ((keep >> lane) & 1) {
            int rk = __popc(keep & ((1u << lane) - 1u));
            ln[mq + rk] = nodel; li[mq + rk] = idx;
            qn[idx] = (u16)(raw | 0x8000);
        }
        __syncwarp();
        mq += cnt;
        if (firstdef >= 0 && rewind < 0) rewind = firstdef;
        pos += bl;
        if (clip < 33) break;
    }
    __syncwarp();
    int key = -(lane + 1), idxe = 0;
    if (lane < mq) {
        idxe = li[lane];
        key = (idxe < NSTART) ? idxe : NSTART + ((idxe - NSTART) >> 4);
    }
    unsigned pk = __match_any_sync(~0u, key);
    int leader = __ffs(pk) - 1;
    unsigned lm = __ballot_sync(~0u, (leader == lane) && (lane < mq));
    int nsl = __popc(lm);
    if (lane < mq) {
        int slot = __popc(lm & ((1u << leader) - 1u));
        sl[lane] = slot;
        if (leader == lane) mi[slot] = idxe;
    }
    __syncwarp();
    bool isnew = false;
    if (lane < nsl) {
        int mx = mi[lane];
        isnew = (mx >= NSTART) && !mats[(mx - NSTART) >> 4];
    }
    unsigned nb = __ballot_sync(~0u, isnew);
    if (isnew) nw[__popc(nb & ((1u << lane) - 1u))] = lane;
    if (lane == 0) {
        ctl[0] = (rewind >= 0) ? rewind : pos;
        ctl[4] = mq; ctl[5] = nsl; ctl[6] = __popc(nb);
        if (mq == 0) ctl[3] = 1;
    }
}

__global__ void __launch_bounds__(1024, 1) serial_kernel(
    const float* __restrict__ fm,  const int*   __restrict__ nbr,
    const float* __restrict__ nsw, const float* __restrict__ nsb,
    const float* __restrict__ nmw, const float* __restrict__ nmb,
    const float* __restrict__ aw,  const float* __restrict__ ab)
{
    extern __shared__ float sm[];
    ull*   s_nsw2 = (ull*)(sm + OFF_NSW);
    ull*   s_part2= (ull*)(sm + OFF_PART);
    float* s_xf   = sm + OFF_XF;
    float* s_xm   = sm + OFF_XM;
    u16*   s_qn16 = (u16*)(sm + OFF_QN);
    float* s_tact = sm + OFF_TACT;
    float* s_aw   = sm + OFF_AW;
    float* s_nsb  = sm + OFF_NSB;
    float* s_nmb  = sm + OFF_NMB;
    float* s_g    = sm + OFF_G;
    int*   s_nbr  = (int*)(sm + OFF_NBR);
    float* s_na   = sm + OFF_NA;
    float* s_actp = sm + OFF_ACTP;
    float* s_actm = sm + OFF_ACTM;
    u8*    s_mats = (u8*)(sm + OFF_MATS);
    int*   ctl    = (int*)(sm + OFF_CTL);

    const int t = threadIdx.x;
    const int w = t >> 5, l = t & 31;

    for (int i = t; i < (256*Hh)/4; i += 1024)
        ((float4*)(sm + OFF_NSW))[i] = ((const float4*)nsw)[i];
    if (t < 256) s_aw[t] = aw[t];
    if (t < 128) { s_nsb[t] = nsb[t]; s_nmb[t] = nmb[t]; s_g[t] = 0.f; }
    if (t < Nn)  s_tact[t] = 0.f;
    if (t < NSTART) s_qn16[t] = (u16)t;
    if (t < MSGCAP) s_mats[t] = 0;
    if (t == 0) {
        ctl[0] = 0; ctl[1] = NSTART; ctl[2] = 0; ctl[3] = 0; ctl[6] = 0;
        sm[OFF_AB] = ab[0];
    }
    ull wnm[16];
    {
        int kc = w >> 1, j2 = ((w & 1) << 5) | l;
        #pragma unroll
        for (int i = 0; i < 16; i++) {
            float2 v = *(const float2*)(nmw + (16*kc + i)*Hh + 2*j2);
            wnm[i] = pack2(v.x, v.y);
        }
    }
    __syncthreads();
    if (w == 0) scan_window(sm, l, 0, 0);
    __syncthreads();

    int buf = 0;
    for (;;) {
        if (ctl[3]) break;
        const int m = ctl[4], nsl = ctl[5], nnew = ctl[6];
        const int tail = ctl[1], pcb = ctl[2];
        const int* s_ln    = (const int*)(sm + OFF_LN)   + buf*Bw;
        const int* s_slotb = (const int*)(sm + OFF_SLOT) + buf*Bw;
        const int* s_midxb = (const int*)(sm + OFF_MIDX) + buf*Bw;
        const int* s_newl  = (const int*)(sm + OFF_NEWL) + buf*Bw;

        // ---- G0 ----
        {
            int k = t & 127, wig = (t >> 5) & 3;
            #pragma unroll
            for (int h2 = 0; h2 < 2; h2++) {
                int e = (t >> 7) + h2*8;
                if (e < m) {
                    int node = s_ln[e];
                    float f1 = g_feats[node*Hh + k];
                    s_xf[e*128 + k] = f1;
                    float ap = f1 * s_aw[k];
                    TREE(ap);
                    if (l == 0) s_actp[e*4 + wig] = ap;
                    if (k < DEGc) s_nbr[e*DEGc + k] = nbr[node*DEGc + k];
                }
                if (e < nsl) {
                    int midx = s_midxb[e];
                    bool oldok = (midx < NSTART) || s_mats[(midx - NSTART) >> 4];
                    if (oldok) {
                        const float* mp = (midx < NSTART) ? (fm + midx*Mm)
                                         : (g_msgs + ((midx - NSTART) >> 4)*Mm);
                        float f2 = mp[k];
                        s_xm[e*128 + k] = f2;
                        float am = f2 * s_aw[128 + k];
                        TREE(am);
                        if (l == 0) s_actm[e*4 + wig] = am;
                    }
                }
            }
        }
        __syncthreads();

        // ---- on-demand message materialization ----
        for (int c = 0; c*4 < nnew; c++) {
            {
                int kc = w >> 1, j2 = ((w & 1) << 5) | l;
                const float4* xp[4];
                #pragma unroll
                for (int el = 0; el < 4; el++) {
                    int sp = c*4 + el;
                    int p = 0;
                    if (sp < nnew) p = (s_midxb[s_newl[sp]] - NSTART) >> 4;
                    xp[el] = (const float4*)(g_xsave + p*256 + kc*16);
                }
                ull a0=0, a1=0, a2=0, a3=0;
                #pragma unroll
                for (int q = 0; q < 4; q++) {
                    ull w0 = wnm[4*q], w1 = wnm[4*q+1], w2 = wnm[4*q+2], w3 = wnm[4*q+3];
                    float4 x0 = xp[0][q], x1 = xp[1][q], x2 = xp[2][q], x3 = xp[3][q];
                    a0 = fma2(pack2(x0.x,x0.x), w0, a0);
                    a0 = fma2(pack2(x0.y,x0.y), w1, a0);
                    a0 = fma2(pack2(x0.z,x0.z), w2, a0);
                    a0 = fma2(pack2(x0.w,x0.w), w3, a0);
                    a1 = fma2(pack2(x1.x,x1.x), w0, a1);
                    a1 = fma2(pack2(x1.y,x1.y), w1, a1);
                    a1 = fma2(pack2(x1.z,x1.z), w2, a1);
                    a1 = fma2(pack2(x1.w,x1.w), w3, a1);
                    a2 = fma2(pack2(x2.x,x2.x), w0, a2);
                    a2 = fma2(pack2(x2.y,x2.y), w1, a2);
                    a2 = fma2(pack2(x2.z,x2.z), w2, a2);
                    a2 = fma2(pack2(x2.w,x2.w), w3, a2);
                    a3 = fma2(pack2(x3.x,x3.x), w0, a3);
                    a3 = fma2(pack2(x3.y,x3.y), w1, a3);
                    a3 = fma2(pack2(x3.z,x3.z), w2, a3);
                    a3 = fma2(pack2(x3.w,x3.w), w3, a3);
                }
                ull* pp = s_part2 + kc*64 + j2;
                pp[0] = a0; pp[1024] = a1; pp[2048] = a2; pp[3072] = a3;
            }
            __syncthreads();
            if (t < 256) {
                int el = t >> 6, j2 = t & 63, sp = c*4 + el;
                if (sp < nnew) {
                    int slot = s_newl[sp];
                    int p = (s_midxb[slot] - NSTART) >> 4;
                    ull s = s_part2[el*1024 + j2];
                    #pragma unroll
                    for (int kc = 1; kc < 16; kc++)
                        s = add2(s, s_part2[el*1024 + kc*64 + j2]);
                    float2 v = unp(s);
                    float2 o; o.x = v.x + s_nmb[2*j2]; o.y = v.y + s_nmb[2*j2+1];
                    *(float2*)(g_msgs + p*Mm + 2*j2) = o;
                    *(float2*)(s_xm + slot*128 + 2*j2) = o;
                    if (j2 == 0) s_mats[p] = 1;
                }
            }
            __syncthreads();
            if (w < 16) {
                int sp = c*4 + (w >> 2);
                if (sp < nnew) {
                    int slot = s_newl[sp], wig = w & 3;
                    float am = s_xm[slot*128 + wig*32 + l] * s_aw[128 + wig*32 + l];
                    TREE(am);
                    if (l == 0) s_actm[slot*4 + wig] = am;
                }
            }
            __syncthreads();
        }

        // ---- NS: 32 warps, 4 entries/grp (R15 form) ----
        {
            int w15 = w & 15;
            int grp = w15 >> 2, kc = (w15 >> 1) & 1, j2 = ((w15 & 1) << 5) | l;
            const ull* wb; const float4* xb; ull* pb; bool act;
            if (w < 16) {
                wb = s_nsw2 + (size_t)(kc*64)*64 + j2;
                xb = (const float4*)(s_xf + grp*512 + kc*64);
                pb = s_part2 + (size_t)(grp*4)*128 + kc*64 + j2;
                act = (grp*4 < m);
            } else {
                wb = s_nsw2 + (size_t)(128 + kc*64)*64 + j2;
                xb = (const float4*)(s_xm + grp*512 + kc*64);
                pb = s_part2 + 2048 + (size_t)(grp*4)*128 + kc*64 + j2;
                act = (grp*4 < nsl);
            }
            if (act) {
                ull a0=0, a1=0, a2=0, a3=0;
                #pragma unroll
                for (int q = 0; q < 16; q++) {
                    ull w0 = wb[(4*q  )*64], w1 = wb[(4*q+1)*64];
                    ull w2 = wb[(4*q+2)*64], w3 = wb[(4*q+3)*64];
                    float4 x0 = xb[q], x1 = xb[32+q], x2 = xb[64+q], x3 = xb[96+q];
                    a0 = fma2(pack2(x0.x,x0.x), w0, a0);
                    a0 = fma2(pack2(x0.y,x0.y), w1, a0);
                    a0 = fma2(pack2(x0.z,x0.z), w2, a0);
                    a0 = fma2(pack2(x0.w,x0.w), w3, a0);
                    a1 = fma2(pack2(x1.x,x1.x), w0, a1);
                    a1 = fma2(pack2(x1.y,x1.y), w1, a1);
                    a1 = fma2(pack2(x1.z,x1.z), w2, a1);
                    a1 = fma2(pack2(x1.w,x1.w), w3, a1);
                    a2 = fma2(pack2(x2.x,x2.x), w0, a2);
                    a2 = fma2(pack2(x2.y,x2.y), w1, a2);
                    a2 = fma2(pack2(x2.z,x2.z), w2, a2);
                    a2 = fma2(pack2(x2.w,x2.w), w3, a2);
                    a3 = fma2(pack2(x3.x,x3.x), w0, a3);
                    a3 = fma2(pack2(x3.y,x3.y), w1, a3);
                    a3 = fma2(pack2(x3.z,x3.z), w2, a3);
                    a3 = fma2(pack2(x3.w,x3.w), w3, a3);
                }
                pb[0] = a0; pb[128] = a1; pb[256] = a2; pb[384] = a3;
            }
        }
        __syncthreads();

        // ---- R ----
        if (t < 512) {
            int j2 = t & 63;
            #pragma unroll
            for (int h2 = 0; h2 < 2; h2++) {
                int e = (t >> 6) + h2*8;
                if (e < m) {
                    int sle = s_slotb[e];
                    ull s = s_part2[e*128 + j2];
                    s = add2(s, s_part2[e*128 + 64 + j2]);
                    s = add2(s, s_part2[2048 + sle*128 + j2]);
                    s = add2(s, s_part2[2048 + sle*128 + 64 + j2]);
                    float2 v = unp(s);
                    float2 o;
                    o.x = fmaxf(v.x + s_nsb[2*j2],     0.f);
                    o.y = fmaxf(v.y + s_nsb[2*j2 + 1], 0.f);
                    *(float2*)(s_xf + e*128 + 2*j2) = o;
                }
            }
        } else if (t < 528) {
            int e = t - 512;
            if (e < m) {
                int sle = s_slotb[e];
                float z = sm[OFF_AB]
                        + s_actp[e*4] + s_actp[e*4+1] + s_actp[e*4+2] + s_actp[e*4+3]
                        + s_actm[sle*4] + s_actm[sle*4+1] + s_actm[sle*4+2] + s_actm[sle*4+3];
                float cand = 1.f / (1.f + expf(-z));
                int node = s_ln[e];
                float ta = s_tact[node];
                float na = (ta + cand > 1.0f) ? (1.0f - ta) : cand;
                s_na[e] = na;
                s_tact[node] = ta + na;
            }
        } else if (t >= 640 && t < 896) {
            int rel = t - 640, e = rel >> 4, d = rel & 15;
            if (e < m) {
                int qp = tail + e*DEGc + d;
                if (qp < MAXM) s_qn16[qp] = (u16)s_nbr[e*DEGc + d];
            }
        }
        __syncthreads();

        // ---- C ----
        if (t < 512) {
            int j2 = t & 63;
            #pragma unroll
            for (int h2 = 0; h2 < 2; h2++) {
                int e = (t >> 6) + h2*8;
                if (e < m) {
                    float2 o = *(const float2*)(s_xf + e*128 + 2*j2);
                    *(float2*)(g_feats + s_ln[e]*Hh + 2*j2) = o;
                    *(float2*)(g_xsave + (pcb + e)*256 + 2*j2) = o;
                }
            }
        } else if (t < 640) {
            int k = t - 512;
            float acc = s_g[k];
            #pragma unroll
            for (int e = 0; e < Bw; e++)
                if (e < m) acc = fmaf(s_xf[e*128 + k], s_na[e], acc);
            s_g[k] = acc;
        } else if (t < 960) {
            for (int j = t - 640; j < 2048; j += 320) {
                int e = j >> 7, k = j & 127;
                if (e < m)
                    g_xsave[(pcb + e)*256 + 128 + k] = s_xm[s_slotb[e]*128 + k];
            }
        } else if (w == 31) {
            scan_window(sm, l, m, buf ^ 1);
        }
        __syncthreads();
        buf ^= 1;
    }

    // ---- handoff dump ----
    for (int i = t; i < Nn; i += 1024) g_tact2[i] = s_tact[i];
    for (int i = t; i < MAXM/2; i += 1024)
        ((unsigned*)g_qn2)[i] = ((const unsigned*)s_qn16)[i];
    for (int i = t; i < MSGCAP/4; i += 1024)
        ((unsigned*)g_mats)[i] = ((const unsigned*)s_mats)[i];
    if (t < 128) g_part[Nn*128 + t] = s_g[t];
    if (t == 0) { g_hh[0] = ctl[0]; g_hh[1] = ctl[1]; g_hh[2] = ctl[2]; }
}

// ---- deferred message kernel: one block per message ----
__global__ void __launch_bounds__(64, 1) msg_kernel(
    const float* __restrict__ nmw, const float* __restrict__ nmb)
{
    int t = threadIdx.x;
    int pc = blockIdx.x;
    if (pc >= g_hh[2] || g_mats[pc]) return;
    int j2 = t;
    ull acc[16];
    #pragma unroll
    for (int kc = 0; kc < 16; kc++) {
        ull a = 0ull;
        #pragma unroll
        for (int q = 0; q < 4; q++) {
            float4 x = *(const float4*)(g_xsave + pc*256 + kc*16 + 4*q);
            const ull* wr = (const ull*)(nmw + (kc*16 + 4*q)*Hh + 2*j2);
            a = fma2(pack2(x.x, x.x), wr[0],   a);
            a = fma2(pack2(x.y, x.y), wr[64],  a);
            a = fma2(pack2(x.z, x.z), wr[128], a);
            a = fma2(pack2(x.w, x.w), wr[192], a);
        }
        acc[kc] = a;
    }
    ull s = acc[0];
    #pragma unroll
    for (int kc = 1; kc < 16; kc++) s = add2(s, acc[kc]);
    float2 v = unp(s);
    float2 o; o.x = v.x + nmb[2*j2]; o.y = v.y + nmb[2*j2+1];
    *(float2*)(g_msgs + pc*Mm + 2*j2) = o;
}

// ---- phase 2: one block per node, 256 threads, split-row matvec ----
__global__ void __launch_bounds__(256, 4) tail_kernel(
    const float* __restrict__ fm,
    const float* __restrict__ nsw, const float* __restrict__ nsb,
    const float* __restrict__ aw,  const float* __restrict__ ab)
{
    __shared__ float s_xf[128], s_xm[128], s_aw2[256], s_nsb2[128], s_gl[128];
    __shared__ ull  s_p2[128];          // msg-half partials (a2,a3 per j2)
    __shared__ u16  s_cand[8*64];
    __shared__ u16  s_li[64];
    __shared__ int  s_wc[8];
    __shared__ int  s_c[1];
    __shared__ float s_f[2];

    const int node = blockIdx.x;
    const int t = threadIdx.x, w = t >> 5, l = t & 31;

    if (t < 128) g_part[node*128 + t] = 0.f;
    if (g_tact2[node] > THRv) return;

    if (t < 256) s_aw2[t] = aw[t];
    if (t < 128) { s_nsb2[t] = nsb[t]; s_gl[t] = 0.f; }
    if (t == 0) { s_f[1] = ab[0]; }

    const int head0 = g_hh[0];
    const int lim2  = g_hh[1] < MAXM ? g_hh[1] : MAXM;
    const int total = lim2 - head0;
    const int seg   = (total + 7) >> 3;

    // barrier-free harvest: warp w scans its ascending segment
    {
        int s0 = head0 + w*seg;
        int s1 = s0 + seg; if (s1 > lim2) s1 = lim2;
        int cw = 0;
        for (int base = s0; base < s1; base += 32) {
            int idx = base + l;
            bool v = idx < s1;
            int raw = v ? (int)g_qn2[idx] : -1;
            bool cand = v && (raw == node);       // bit15 clear + node match
            unsigned bal = __ballot_sync(~0u, cand);
            if (cand) {
                int p = cw + __popc(bal & ((1u << l) - 1u));
                if (p < 64) s_cand[w*64 + p] = (u16)idx;
            }
            cw += __popc(bal);
        }
        if (l == 0) s_wc[w] = cw < 64 ? cw : 64;
    }
    __syncthreads();
    if (t == 0) {
        int c = 0;
        for (int q = 0; q < 8; q++)
            for (int i = 0; i < s_wc[q] && c < 64; i++)
                s_li[c++] = s_cand[q*64 + i];
        s_c[0] = c;
    }
    __syncthreads();
    const int cnt = s_c[0];

    float tav = g_tact2[node];
    for (int i = 0; i < cnt; i++) {
        if (tav > THRv) break;
        const int idx = (int)s_li[i];
        if (t < 128) {
            s_xf[t] = g_feats[node*Hh + t];
            const float* mp = (idx < NSTART) ? (fm + idx*Mm)
                             : (g_msgs + ((idx - NSTART) >> 4)*Mm);
            s_xm[t] = mp[t];
        }
        __syncthreads();

        ull a0 = 0ull, a1 = 0ull;
        if (t < 128) {
            const int j2 = t & 63, half = t >> 6;   // half0: feats rows, half1: msg rows
            const ull* wb = (const ull*)nsw + j2 + (size_t)(half*128)*64;
            const float4* xs = half ? (const float4*)s_xm : (const float4*)s_xf;
            #pragma unroll
            for (int h = 0; h < 2; h++) {
                ull a = 0ull;
                const float4* xv = xs + h*16;
                const ull* wh = wb + (size_t)(h*64)*64;
                #pragma unroll
                for (int q = 0; q < 16; q++) {
                    float4 x = xv[q];
                    a = fma2(pack2(x.x, x.x), wh[(4*q  )*64], a);
                    a = fma2(pack2(x.y, x.y), wh[(4*q+1)*64], a);
                    a = fma2(pack2(x.z, x.z), wh[(4*q+2)*64], a);
                    a = fma2(pack2(x.w, x.w), wh[(4*q+3)*64], a);
                }
                if (h == 0) a0 = a; else a1 = a;
            }
            if (half) { s_p2[2*j2] = a0; s_p2[2*j2 + 1] = a1; }
        } else if (w == 5) {
            float pf[4], pm[4];
            #pragma unroll
            for (int g = 0; g < 4; g++) {
                float ap = s_xf[g*32 + l] * s_aw2[g*32 + l];
                TREE(ap); pf[g] = ap;
            }
            #pragma unroll
            for (int g = 0; g < 4; g++) {
                float am = s_xm[g*32 + l] * s_aw2[128 + g*32 + l];
                TREE(am); pm[g] = am;
            }
            if (l == 0) {
                float z = s_f[1] + pf[0] + pf[1] + pf[2] + pf[3]
                                 + pm[0] + pm[1] + pm[2] + pm[3];
                float cd = 1.f / (1.f + expf(-z));
                float na = (tav + cd > 1.0f) ? (1.0f - tav) : cd;
                s_f[0] = na;
            }
        }
        __syncthreads();

        if (t < 64) {
            const int j2 = t;
            ull s = add2(add2(add2(a0, a1), s_p2[2*j2]), s_p2[2*j2 + 1]);
            float2 v = unp(s);
            float2 o;
            o.x = fmaxf(v.x + s_nsb2[2*j2],     0.f);
            o.y = fmaxf(v.y + s_nsb2[2*j2 + 1], 0.f);
            float na = s_f[0];
            *(float2*)(g_feats + node*Hh + 2*j2) = o;
            s_gl[2*j2]     += o.x * na;
            s_gl[2*j2 + 1] += o.y * na;
        }
        tav += s_f[0];
        __syncthreads();
    }

    if (t == 0) g_tact2[node] = tav;
    if (t < 128) g_part[node*128 + t] = s_gl[t];
}

__global__ void __launch_bounds__(1024, 1) decode_kernel(
    const float* __restrict__ dw, const float* __restrict__ db,
    float* __restrict__ out)
{
    __shared__ float sp2[8*128];
    __shared__ float sg[128];
    __shared__ float sc[32];
    int t = threadIdx.x;
    {
        int col = t & 127, seg = t >> 7;
        float a = 0.f;
        for (int b = seg; b <= Nn; b += 8) a += g_part[b*128 + col];
        sp2[seg*128 + col] = a;
    }
    __syncthreads();
    if (t < 128) {
        float a = sp2[t];
        #pragma unroll
        for (int s = 1; s < 8; s++) a += sp2[s*128 + t];
        sg[t] = a;
    }
    __syncthreads();
    if (t < Pp*OUTn) {
        int p = t / OUTn, o = t % OUTn;
        float z = db[p*OUTn + o];
        #pragma unroll 8
        for (int h = 0; h < Hh; h++) z = fmaf(sg[h], dw[(p*Hh + h)*OUTn + o], z);
        sc[t] = z;
    }
    __syncthreads();
    if (t < Pp) {
        float mx = -1e30f;
        for (int o = 0; o < OUTn; o++) mx = fmaxf(mx, sc[t*OUTn + o]);
        float se = 0.f;
        for (int o = 0; o < OUTn; o++) se += expf(sc[t*OUTn + o] - mx);
        float ls = logf(se);
        for (int o = 0; o < OUTn; o++) out[t*OUTn + o] = sc[t*OUTn + o] - mx - ls;
    }
}

extern "C" void kernel_launch(void* const* d_in, const int* in_sizes, int n_in,
                              void* d_out, int out_size)
{
    const float* xa  = (const float*)d_in[0];
    const float* fm  = (const float*)d_in[1];
    const int*   nbv = (const int*)  d_in[2];
    const float* ew  = (const float*)d_in[4];
    const float* eb  = (const float*)d_in[5];
    const float* nsw = (const float*)d_in[6];
    const float* nsb = (const float*)d_in[7];
    const float* nmw = (const float*)d_in[8];
    const float* nmb = (const float*)d_in[9];
    const float* aw  = (const float*)d_in[10];
    const float* ab  = (const float*)d_in[11];
    const float* dw  = (const float*)d_in[12];
    const float* db  = (const float*)d_in[13];
    float* out = (float*)d_out;

    cudaFuncSetAttribute(serial_kernel,
                         cudaFuncAttributeMaxDynamicSharedMemorySize, SMEM_BYTES);

    enc_kernel<<<Nn, Hh>>>(xa, ew, eb);
    serial_kernel<<<1, 1024, SMEM_BYTES>>>(fm, nbv, nsw, nsb, nmw, nmb, aw, ab);
    msg_kernel<<<MSGCAP, 64>>>(nmw, nmb);
    tail_kernel<<<Nn, 256>>>(fm, nsw, nsb, aw, ab);
    decode_kernel<<<1, 1024>>>(dw, db, out);
}